// round 12
// baseline (speedup 1.0000x reference)
#include <cuda_runtime.h>
#include <math.h>

// B=32, J=16, L=4096, MU_P=0.15, MASK_ID=103
#define ROW_LEN   4096
#define THREADS   512
#define EPT       8
#define MASK_ID_F 103.0f
#define FULLMASK  0xFFFFFFFFu

__global__ void __launch_bounds__(THREADS, 4)
gumbel_topk_mask_kernel(const int*   __restrict__ ids,
                        const float* __restrict__ msk2,   // (rows, 2*L)
                        const float* __restrict__ uu,     // (rows, L)
                        float*       __restrict__ out,    // (3, rows, L)
                        int N)
{
    __shared__ unsigned int hist12[2][4096]; // 12-bit passes (32KB), cleared once
    __shared__ unsigned int hist8[256];      // final 8-bit pass (1KB)
    __shared__ int          s_wt[16];        // warp totals (block scan)
    __shared__ int          s_warpsum[16];   // phase-3 scan
    __shared__ unsigned int s_prefix;
    __shared__ int          s_kk;

    const int t    = threadIdx.x;
    const int lane = t & 31;
    const int warp = t >> 5;
    const int row  = blockIdx.x;
    const int base = row * ROW_LEN;          // fits int

    const float* wrow = msk2 + row * (2 * ROW_LEN);
    const float* urow = uu   + base;
    const int*   irow = ids  + base;

    // Clear histograms (8192 words as uint4 + 256 words)
    {
        uint4* hp = reinterpret_cast<uint4*>(&hist12[0][0]);
        uint4 z = make_uint4(0u, 0u, 0u, 0u);
        hp[t] = z; hp[t + 512] = z; hp[t + 1024] = z; hp[t + 1536] = z;
        if (t < 256) hist8[t] = 0u;
    }

    // ---- Phase 1: build sortable keys.
    // order(score) == order( max(w,1e-30) / (-log u) ); r>0 so
    // bits(r)|0x80000000 is order-preserving. key==0 marks excluded (w<=0).
    unsigned int mykeys[EPT];
    #pragma unroll
    for (int g = 0; g < 2; g++) {
        float4 w4 = reinterpret_cast<const float4*>(wrow)[t * 2 + g];
        float4 u4 = reinterpret_cast<const float4*>(urow)[t * 2 + g];
        #pragma unroll
        for (int j = 0; j < 4; j++) {
            float w = (j == 0) ? w4.x : (j == 1) ? w4.y : (j == 2) ? w4.z : w4.w;
            float u = (j == 0) ? u4.x : (j == 1) ? u4.y : (j == 2) ? u4.z : u4.w;
            unsigned int key = 0u;
            if (w > 0.0f) {
                float nl = -__logf(u);                        // > 0 (u<1)
                float r  = __fdividef(fmaxf(w, 1e-30f), nl);  // > 0 finite
                key = __float_as_uint(r) | 0x80000000u;
            }
            mykeys[g * 4 + j] = key;
        }
    }
    __syncthreads();   // clears done, keys ready

    unsigned int prefixReg = 0u;
    int          kkReg     = 0;

    // ---- Phase 2a: two 12-bit passes (block-parallel 4096-bin suffix scan)
    #pragma unroll
    for (int pass = 0; pass < 2; pass++) {
        if (pass == 0) {
            #pragma unroll
            for (int j = 0; j < EPT; j++) {
                unsigned int key = mykeys[j];
                if (key != 0u) atomicAdd(&hist12[0][key >> 20], 1u);
            }
        } else {
            #pragma unroll
            for (int j = 0; j < EPT; j++) {
                unsigned int key = mykeys[j];
                if (((key ^ prefixReg) >> 20) == 0u)
                    atomicAdd(&hist12[1][(key >> 8) & 0xFFFu], 1u);
            }
        }
        __syncthreads();

        // thread owns 8 bins
        unsigned int v[8];
        unsigned int tot = 0u;
        #pragma unroll
        for (int i = 0; i < 8; i++) { v[i] = hist12[pass][t * 8 + i]; tot += v[i]; }

        unsigned int run = tot;                       // inclusive lane-suffix
        #pragma unroll
        for (int off = 1; off < 32; off <<= 1) {
            unsigned int o = __shfl_down_sync(FULLMASK, run, off);
            if (lane + off < 32) run += o;
        }
        if (lane == 0) s_wt[warp] = (int)run;
        unsigned int laneAbove = run - tot;
        __syncthreads();

        int total = 0, aboveW = 0;
        #pragma unroll
        for (int w = 0; w < 16; w++) {
            int x = s_wt[w];
            total += x;
            if (w > warp) aboveW += x;
        }

        int kkPass = (pass == 0) ? (int)floorf(0.15f * (float)total) : kkReg;

        if (kkPass > 0) {
            unsigned int sufRun = (unsigned int)aboveW + laneAbove;
            #pragma unroll
            for (int i = 7; i >= 0; i--) {
                sufRun += v[i];                       // count(digit >= bin i)
                unsigned int cgt = sufRun - v[i];     // count(digit >  bin i)
                if ((int)cgt < kkPass && kkPass <= (int)sufRun) {
                    unsigned int d = (unsigned int)(t * 8 + i);
                    s_prefix = (pass == 0) ? (d << 20) : (prefixReg | (d << 8));
                    s_kk     = kkPass - (int)cgt;
                }
            }
        } else if (t == 0) {
            s_prefix = 0xFFFFFFFFu;                   // k==0: select nothing
            s_kk     = 0;
        }
        __syncthreads();
        prefixReg = s_prefix;
        kkReg     = s_kk;
    }

    // ---- Phase 2b: final 8-bit pass (low byte), warp-0 scan of 256 bins
    {
        #pragma unroll
        for (int j = 0; j < EPT; j++) {
            unsigned int key = mykeys[j];
            if ((key & 0xFFFFFF00u) == prefixReg)
                atomicAdd(&hist8[key & 0xFFu], 1u);
        }
        __syncthreads();

        if (warp == 0) {
            unsigned int v[8], lsuf[8];
            #pragma unroll
            for (int i = 0; i < 8; i++) v[i] = hist8[lane * 8 + i];
            unsigned int tot = 0u;
            #pragma unroll
            for (int i = 7; i >= 0; i--) { tot += v[i]; lsuf[i] = tot; }

            unsigned int run = tot;
            #pragma unroll
            for (int off = 1; off < 32; off <<= 1) {
                unsigned int o = __shfl_down_sync(FULLMASK, run, off);
                if (lane + off < 32) run += o;
            }
            unsigned int above = run - tot;

            int kkPass = kkReg;
            if (kkPass > 0) {
                #pragma unroll
                for (int i = 0; i < 8; i++) {
                    unsigned int suf = lsuf[i] + above;
                    unsigned int cgt = suf - v[i];
                    if ((int)cgt < kkPass && kkPass <= (int)suf) {
                        s_prefix = prefixReg | (unsigned int)(lane * 8 + i);
                        s_kk     = kkPass - (int)cgt;
                    }
                }
            } else if (lane == 0) {
                s_prefix = 0xFFFFFFFFu;
                s_kk     = 0;
            }
        }
        __syncthreads();
    }

    const unsigned int T = s_prefix;    // exact k-th largest key
    const int need_eq    = s_kk;        // # of key==T to take, lowest index first

    // ---- Phase 3: stable tie-break — exclusive scan of (key==T) counts
    int myEq = 0;
    #pragma unroll
    for (int j = 0; j < EPT; j++) myEq += (mykeys[j] == T) ? 1 : 0;

    int incl = myEq;
    #pragma unroll
    for (int off = 1; off < 32; off <<= 1) {
        int o = __shfl_up_sync(FULLMASK, incl, off);
        if (lane >= off) incl += o;
    }
    if (lane == 31) s_warpsum[warp] = incl;
    __syncthreads();
    int woff = 0;
    #pragma unroll
    for (int w = 0; w < 16; w++)
        woff += (w < warp) ? s_warpsum[w] : 0;
    int running = woff + (incl - myEq);

    // ---- Phase 4: selection + outputs (32-bit addressing)
    float4* o_ids = reinterpret_cast<float4*>(out + base);
    float4* o_m   = reinterpret_cast<float4*>(out + N + base);
    float4* o_nm  = reinterpret_cast<float4*>(out + 2 * N + base);

    #pragma unroll
    for (int g = 0; g < 2; g++) {
        int4 iv4 = reinterpret_cast<const int4*>(irow)[t * 2 + g];
        float oid[4], om[4], onm[4];
        #pragma unroll
        for (int j = 0; j < 4; j++) {
            int iv = (j == 0) ? iv4.x : (j == 1) ? iv4.y : (j == 2) ? iv4.z : iv4.w;
            unsigned int key = mykeys[g * 4 + j];
            bool sel = false;
            if (key > T) sel = true;
            else if (key == T) { sel = (running < need_eq); running++; }
            oid[j] = sel ? MASK_ID_F : (float)iv;
            om[j]  = sel ? 1.0f : 0.0f;
            onm[j] = sel ? -1.0f : -0.0f;
        }
        o_ids[t * 2 + g] = make_float4(oid[0], oid[1], oid[2], oid[3]);
        o_m  [t * 2 + g] = make_float4(om[0],  om[1],  om[2],  om[3]);
        o_nm [t * 2 + g] = make_float4(onm[0], onm[1], onm[2], onm[3]);
    }
}

extern "C" void kernel_launch(void* const* d_in, const int* in_sizes, int n_in,
                              void* d_out, int out_size)
{
    const int*   ids  = (const int*)d_in[0];
    const float* msk2 = (const float*)d_in[1];
    const float* u    = (const float*)d_in[2];
    float*       out  = (float*)d_out;

    const int N    = in_sizes[0];
    const int rows = N / ROW_LEN;

    gumbel_topk_mask_kernel<<<rows, THREADS>>>(ids, msk2, u, out, N);
}

// round 13
// speedup vs baseline: 1.0046x; 1.0046x over previous
#include <cuda_runtime.h>
#include <math.h>

// B=32, J=16, L=4096, MU_P=0.15, MASK_ID=103
#define ROW_LEN   4096
#define THREADS   512
#define EPT       8
#define MASK_ID_F 103.0f
#define FULLMASK  0xFFFFFFFFu

__global__ void __launch_bounds__(THREADS, 2)
gumbel_topk_mask_kernel(const int*   __restrict__ ids,
                        const float* __restrict__ msk2,   // (rows, 2*L)
                        const float* __restrict__ uu,     // (rows, L)
                        float*       __restrict__ out,    // (3, rows, L)
                        int N)
{
    __shared__ __align__(16) int s_ids[2][ROW_LEN];   // 32KB prefetched ids
    __shared__ unsigned int hist[2][4][256];          // 8KB, cleared once
    __shared__ unsigned int s_prefix[2];
    __shared__ int          s_kk[2];
    __shared__ int          s_warpsum[2][16];

    const int t    = threadIdx.x;
    const int lane = t & 31;
    const int warp = t >> 5;
    const int rowA = blockIdx.x * 2;
    const int baseA = rowA * ROW_LEN;
    const int baseB = baseA + ROW_LEN;

    // ---- Prefetch ids for both rows (each thread copies its own 32B/row)
    {
        unsigned long long sdA = __cvta_generic_to_shared(&s_ids[0][t * EPT]);
        unsigned long long sdB = __cvta_generic_to_shared(&s_ids[1][t * EPT]);
        const int* gA = ids + baseA + t * EPT;
        const int* gB = ids + baseB + t * EPT;
        asm volatile("cp.async.cg.shared.global [%0], [%1], 16;\n" :: "l"(sdA), "l"(gA));
        asm volatile("cp.async.cg.shared.global [%0], [%1], 16;\n" :: "l"(sdA + 16), "l"(gA + 4));
        asm volatile("cp.async.cg.shared.global [%0], [%1], 16;\n" :: "l"(sdB), "l"(gB));
        asm volatile("cp.async.cg.shared.global [%0], [%1], 16;\n" :: "l"(sdB + 16), "l"(gB + 4));
        asm volatile("cp.async.commit_group;\n");
    }

    // Clear histograms: 2048 words, 4 per thread
    {
        unsigned int* hp = &hist[0][0][0];
        hp[t] = 0u; hp[t + 512] = 0u; hp[t + 1024] = 0u; hp[t + 1536] = 0u;
    }

    // ---- Phase 1: build keys for both rows.
    // order(score) == order( max(w,1e-30) / (-log u) ); r>0 so
    // bits(r)|0x80000000 is order-preserving; key==0 marks excluded (w<=0).
    unsigned int keyA[EPT], keyB[EPT];
    #pragma unroll
    for (int r = 0; r < 2; r++) {
        const float* wrow = msk2 + (rowA + r) * (2 * ROW_LEN);
        const float* urow = uu + (r == 0 ? baseA : baseB);
        unsigned int* kk = (r == 0) ? keyA : keyB;
        #pragma unroll
        for (int g = 0; g < 2; g++) {
            float4 w4 = reinterpret_cast<const float4*>(wrow)[t * 2 + g];
            float4 u4 = reinterpret_cast<const float4*>(urow)[t * 2 + g];
            #pragma unroll
            for (int j = 0; j < 4; j++) {
                float w = (j == 0) ? w4.x : (j == 1) ? w4.y : (j == 2) ? w4.z : w4.w;
                float u = (j == 0) ? u4.x : (j == 1) ? u4.y : (j == 2) ? u4.z : u4.w;
                unsigned int key = 0u;
                if (w > 0.0f) {
                    float nl = -__logf(u);
                    float rr = __fdividef(fmaxf(w, 1e-30f), nl);
                    key = __float_as_uint(rr) | 0x80000000u;
                }
                kk[g * 4 + j] = key;
            }
        }
    }
    __syncthreads();   // clears done, keys ready

    // ---- Phase 2: 4-pass radix-select, both rows per pass
    unsigned int prefA = 0u, prefB = 0u;
    int kkA = 0, kkB = 0;

    #pragma unroll
    for (int pass = 0; pass < 4; pass++) {
        const int shift = 24 - 8 * pass;

        if (pass == 0) {
            #pragma unroll
            for (int j = 0; j < EPT; j++) {
                if (keyA[j] != 0u) atomicAdd(&hist[0][0][keyA[j] >> 24], 1u);
                if (keyB[j] != 0u) atomicAdd(&hist[1][0][keyB[j] >> 24], 1u);
            }
        } else {
            #pragma unroll
            for (int j = 0; j < EPT; j++) {
                if ((keyA[j] ^ prefA) >> (shift + 8) == 0u)
                    atomicAdd(&hist[0][pass][(keyA[j] >> shift) & 255u], 1u);
                if ((keyB[j] ^ prefB) >> (shift + 8) == 0u)
                    atomicAdd(&hist[1][pass][(keyB[j] >> shift) & 255u], 1u);
            }
        }
        __syncthreads();

        // warp 0 scans row A, warp 8 (other SMSP) scans row B — in parallel
        if (warp == 0 || warp == 8) {
            const int r = warp >> 3;
            const unsigned int prefR = (r == 0) ? prefA : prefB;
            const int kkRin = (r == 0) ? kkA : kkB;

            unsigned int v[8], lsuf[8];
            #pragma unroll
            for (int i = 0; i < 8; i++) v[i] = hist[r][pass][lane * 8 + i];
            unsigned int tot = 0u;
            #pragma unroll
            for (int i = 7; i >= 0; i--) { tot += v[i]; lsuf[i] = tot; }

            unsigned int run = tot;
            #pragma unroll
            for (int off = 1; off < 32; off <<= 1) {
                unsigned int o = __shfl_down_sync(FULLMASK, run, off);
                if (lane + off < 32) run += o;
            }
            unsigned int above = run - tot;

            int kkPass;
            if (pass == 0) {
                unsigned int cnt = __shfl_sync(FULLMASK, run, 0);
                kkPass = (int)floorf(0.15f * (float)cnt);
                if (lane == 0 && kkPass <= 0) { s_prefix[r] = 0xFFFFFFFFu; s_kk[r] = 0; }
            } else {
                kkPass = kkRin;
            }

            if (kkPass > 0) {
                #pragma unroll
                for (int i = 0; i < 8; i++) {
                    unsigned int suf = lsuf[i] + above;
                    unsigned int cgt = suf - v[i];
                    if ((int)cgt < kkPass && kkPass <= (int)suf) {
                        s_prefix[r] = prefR | ((unsigned int)(lane * 8 + i) << shift);
                        s_kk[r]     = kkPass - (int)cgt;
                    }
                }
            }
        }
        __syncthreads();
        prefA = s_prefix[0]; kkA = s_kk[0];
        prefB = s_prefix[1]; kkB = s_kk[1];
    }

    const unsigned int TA = prefA, TB = prefB;
    const int needA = kkA, needB = kkB;

    // ---- Phase 3: stable tie-break for both rows (one barrier)
    int eqA = 0, eqB = 0;
    #pragma unroll
    for (int j = 0; j < EPT; j++) {
        eqA += (keyA[j] == TA) ? 1 : 0;
        eqB += (keyB[j] == TB) ? 1 : 0;
    }
    int inclA = eqA, inclB = eqB;
    #pragma unroll
    for (int off = 1; off < 32; off <<= 1) {
        int oA = __shfl_up_sync(FULLMASK, inclA, off);
        int oB = __shfl_up_sync(FULLMASK, inclB, off);
        if (lane >= off) { inclA += oA; inclB += oB; }
    }
    if (lane == 31) { s_warpsum[0][warp] = inclA; s_warpsum[1][warp] = inclB; }
    __syncthreads();
    int woffA = 0, woffB = 0;
    #pragma unroll
    for (int w = 0; w < 16; w++) {
        if (w < warp) { woffA += s_warpsum[0][w]; woffB += s_warpsum[1][w]; }
    }
    int runA = woffA + (inclA - eqA);
    int runB = woffB + (inclB - eqB);

    // ---- Phase 4: selection + outputs for both rows
    asm volatile("cp.async.wait_group 0;\n");

    #pragma unroll
    for (int r = 0; r < 2; r++) {
        const int base = (r == 0) ? baseA : baseB;
        const unsigned int* kk = (r == 0) ? keyA : keyB;
        const unsigned int T = (r == 0) ? TA : TB;
        const int need = (r == 0) ? needA : needB;
        int running = (r == 0) ? runA : runB;

        float4* o_ids = reinterpret_cast<float4*>(out + base);
        float4* o_m   = reinterpret_cast<float4*>(out + N + base);
        float4* o_nm  = reinterpret_cast<float4*>(out + 2 * N + base);

        #pragma unroll
        for (int g = 0; g < 2; g++) {
            int4 iv4 = reinterpret_cast<const int4*>(&s_ids[r][t * EPT])[g];
            float oid[4], om[4], onm[4];
            #pragma unroll
            for (int j = 0; j < 4; j++) {
                int iv = (j == 0) ? iv4.x : (j == 1) ? iv4.y : (j == 2) ? iv4.z : iv4.w;
                unsigned int key = kk[g * 4 + j];
                bool sel = false;
                if (key > T) sel = true;
                else if (key == T) { sel = (running < need); running++; }
                oid[j] = sel ? MASK_ID_F : (float)iv;
                om[j]  = sel ? 1.0f : 0.0f;
                onm[j] = sel ? -1.0f : -0.0f;
            }
            o_ids[t * 2 + g] = make_float4(oid[0], oid[1], oid[2], oid[3]);
            o_m  [t * 2 + g] = make_float4(om[0],  om[1],  om[2],  om[3]);
            o_nm [t * 2 + g] = make_float4(onm[0], onm[1], onm[2], onm[3]);
        }
    }
}

extern "C" void kernel_launch(void* const* d_in, const int* in_sizes, int n_in,
                              void* d_out, int out_size)
{
    const int*   ids  = (const int*)d_in[0];
    const float* msk2 = (const float*)d_in[1];
    const float* u    = (const float*)d_in[2];
    float*       out  = (float*)d_out;

    const int N    = in_sizes[0];
    const int rows = N / ROW_LEN;

    gumbel_topk_mask_kernel<<<rows / 2, THREADS>>>(ids, msk2, u, out, N);
}

// round 14
// speedup vs baseline: 1.0880x; 1.0831x over previous
#include <cuda_runtime.h>
#include <math.h>

// B=32, J=16, L=4096, MU_P=0.15, MASK_ID=103
#define ROW_LEN   4096
#define THREADS   512
#define EPT       8
#define MASK_ID_F 103.0f
#define FULLMASK  0xFFFFFFFFu

__global__ void __launch_bounds__(THREADS, 4)
gumbel_topk_mask_kernel(const int*   __restrict__ ids,
                        const float* __restrict__ msk2,   // (rows, 2*L)
                        const float* __restrict__ uu,     // (rows, L)
                        float*       __restrict__ out,    // (3, rows, L)
                        int N)
{
    __shared__ unsigned int hist[2][256];    // passes 0,1 (2KB)
    __shared__ unsigned int s_list[ROW_LEN]; // compacted candidates (16KB, worst case)
    __shared__ unsigned int s_n;
    __shared__ unsigned int s_prefix;
    __shared__ int          s_kk;
    __shared__ int          s_warpsum[16];

    const int t    = threadIdx.x;
    const int lane = t & 31;
    const int warp = t >> 5;
    const int row  = blockIdx.x;
    const int base = row * ROW_LEN;          // fits int

    const float* wrow = msk2 + row * (2 * ROW_LEN);
    const float* urow = uu   + base;
    const int*   irow = ids  + base;

    // Clear both histograms (512 words, 1 per thread) + counter
    ((unsigned int*)hist)[t] = 0u;
    if (t == 0) s_n = 0u;

    // ---- Phase 1: build sortable keys.
    // order(score) == order( max(w,1e-30) / (-log u) ); r>0 so
    // bits(r)|0x80000000 is order-preserving. key==0 marks excluded (w<=0).
    unsigned int mykeys[EPT];
    #pragma unroll
    for (int g = 0; g < 2; g++) {
        float4 w4 = reinterpret_cast<const float4*>(wrow)[t * 2 + g];
        float4 u4 = reinterpret_cast<const float4*>(urow)[t * 2 + g];
        #pragma unroll
        for (int j = 0; j < 4; j++) {
            float w = (j == 0) ? w4.x : (j == 1) ? w4.y : (j == 2) ? w4.z : w4.w;
            float u = (j == 0) ? u4.x : (j == 1) ? u4.y : (j == 2) ? u4.z : u4.w;
            unsigned int key = 0u;
            if (w > 0.0f) {
                float nl = -__logf(u);                        // > 0 (u<1)
                float r  = __fdividef(fmaxf(w, 1e-30f), nl);  // > 0 finite
                key = __float_as_uint(r) | 0x80000000u;
            }
            mykeys[g * 4 + j] = key;
        }
    }
    __syncthreads();   // clears done, keys ready

    // ---- Phase 2: two 8-bit radix passes -> exact top-16-bit prefix
    unsigned int prefixReg = 0u;
    int          kkReg     = 0;

    #pragma unroll
    for (int pass = 0; pass < 2; pass++) {
        const int shift = 24 - 8 * pass;

        if (pass == 0) {
            #pragma unroll
            for (int j = 0; j < EPT; j++) {
                unsigned int key = mykeys[j];
                if (key != 0u) atomicAdd(&hist[0][key >> 24], 1u);
            }
        } else {
            #pragma unroll
            for (int j = 0; j < EPT; j++) {
                unsigned int key = mykeys[j];
                if ((key ^ prefixReg) >> 24 == 0u)
                    atomicAdd(&hist[1][(key >> 16) & 255u], 1u);
            }
        }
        __syncthreads();

        if (warp == 0) {
            // lane owns 8 consecutive bins; warp-local suffix sums
            unsigned int v[8], lsuf[8];
            #pragma unroll
            for (int i = 0; i < 8; i++) v[i] = hist[pass][lane * 8 + i];
            unsigned int tot = 0u;
            #pragma unroll
            for (int i = 7; i >= 0; i--) { tot += v[i]; lsuf[i] = tot; }

            unsigned int run = tot;
            #pragma unroll
            for (int off = 1; off < 32; off <<= 1) {
                unsigned int o = __shfl_down_sync(FULLMASK, run, off);
                if (lane + off < 32) run += o;
            }
            unsigned int above = run - tot;   // sum over lanes > lane

            int kkPass;
            if (pass == 0) {
                unsigned int cnt = __shfl_sync(FULLMASK, run, 0);   // total nonzero
                kkPass = (int)floorf(0.15f * (float)cnt);
                if (lane == 0 && kkPass <= 0) { s_prefix = 0xFFFFFFFFu; s_kk = 0; }
            } else {
                kkPass = kkReg;
            }

            if (kkPass > 0) {
                #pragma unroll
                for (int i = 0; i < 8; i++) {
                    unsigned int suf = lsuf[i] + above;   // count(byte >= bin)
                    unsigned int cgt = suf - v[i];        // count(byte >  bin)
                    if ((int)cgt < kkPass && kkPass <= (int)suf) {
                        s_prefix = prefixReg | ((unsigned int)(lane * 8 + i) << shift);
                        s_kk     = kkPass - (int)cgt;
                    }
                }
            }
        }
        __syncthreads();
        prefixReg = s_prefix;
        kkReg     = s_kk;
    }

    // ---- Phase 2b: compact keys matching the 16-bit prefix into s_list
    #pragma unroll
    for (int j = 0; j < EPT; j++) {
        unsigned int key = mykeys[j];
        if ((key & 0xFFFF0000u) == prefixReg) {
            unsigned int idx = atomicAdd(&s_n, 1u);
            s_list[idx] = key;
        }
    }
    __syncthreads();

    // ---- Phase 2c: warp 0 finds the kk-th largest among n candidates.
    // Exact for any input: repeated max-extraction with duplicate counting.
    if (warp == 0) {
        int n = (int)s_n;
        int remaining = kkReg;
        if (remaining > 0) {
            unsigned int limit = 0xFFFFFFFFu;   // keys < 0xFFFFFFFF always
            for (;;) {
                unsigned int M = 0u;
                for (int i = lane; i < n; i += 32) {
                    unsigned int x = s_list[i];
                    if (x < limit) M = max(M, x);
                }
                #pragma unroll
                for (int off = 16; off; off >>= 1)
                    M = max(M, __shfl_xor_sync(FULLMASK, M, off));
                int c = 0;
                for (int i = lane; i < n; i += 32)
                    c += (s_list[i] == M) ? 1 : 0;
                #pragma unroll
                for (int off = 16; off; off >>= 1)
                    c += __shfl_xor_sync(FULLMASK, c, off);
                if (remaining <= c) {
                    if (lane == 0) { s_prefix = M; s_kk = remaining; }
                    break;
                }
                remaining -= c;
                limit = M;
            }
        }
    }
    __syncthreads();

    const unsigned int T = s_prefix;    // exact k-th largest key
    const int need_eq    = s_kk;        // # of key==T to take, lowest index first

    // ---- Phase 3: stable tie-break — exclusive scan of (key==T) counts
    int myEq = 0;
    #pragma unroll
    for (int j = 0; j < EPT; j++) myEq += (mykeys[j] == T) ? 1 : 0;

    int incl = myEq;
    #pragma unroll
    for (int off = 1; off < 32; off <<= 1) {
        int o = __shfl_up_sync(FULLMASK, incl, off);
        if (lane >= off) incl += o;
    }
    if (lane == 31) s_warpsum[warp] = incl;
    __syncthreads();
    int woff = 0;
    #pragma unroll
    for (int w = 0; w < 16; w++)
        woff += (w < warp) ? s_warpsum[w] : 0;
    int running = woff + (incl - myEq);

    // ---- Phase 4: selection + outputs (32-bit addressing)
    float4* o_ids = reinterpret_cast<float4*>(out + base);
    float4* o_m   = reinterpret_cast<float4*>(out + N + base);
    float4* o_nm  = reinterpret_cast<float4*>(out + 2 * N + base);

    #pragma unroll
    for (int g = 0; g < 2; g++) {
        int4 iv4 = reinterpret_cast<const int4*>(irow)[t * 2 + g];
        float oid[4], om[4], onm[4];
        #pragma unroll
        for (int j = 0; j < 4; j++) {
            int iv = (j == 0) ? iv4.x : (j == 1) ? iv4.y : (j == 2) ? iv4.z : iv4.w;
            unsigned int key = mykeys[g * 4 + j];
            bool sel = false;
            if (key > T) sel = true;
            else if (key == T) { sel = (running < need_eq); running++; }
            oid[j] = sel ? MASK_ID_F : (float)iv;
            om[j]  = sel ? 1.0f : 0.0f;
            onm[j] = sel ? -1.0f : -0.0f;
        }
        o_ids[t * 2 + g] = make_float4(oid[0], oid[1], oid[2], oid[3]);
        o_m  [t * 2 + g] = make_float4(om[0],  om[1],  om[2],  om[3]);
        o_nm [t * 2 + g] = make_float4(onm[0], onm[1], onm[2], onm[3]);
    }
}

extern "C" void kernel_launch(void* const* d_in, const int* in_sizes, int n_in,
                              void* d_out, int out_size)
{
    const int*   ids  = (const int*)d_in[0];
    const float* msk2 = (const float*)d_in[1];
    const float* u    = (const float*)d_in[2];
    float*       out  = (float*)d_out;

    const int N    = in_sizes[0];
    const int rows = N / ROW_LEN;

    gumbel_topk_mask_kernel<<<rows, THREADS>>>(ids, msk2, u, out, N);
}